// round 13
// baseline (speedup 1.0000x reference)
#include <cuda_runtime.h>
#include <math_constants.h>

#define BD   64
#define MAXB 8192
#define MAXM 16384
#define TS   132   // smem row stride (floats) for transposed tiles

// ---------------- device scratch (static: no allocations allowed) ----------
__device__ float g_an[MAXB * BD];                    // normalized anchors
__device__ float g_cn[MAXM * BD];                    // normalized candidates (pos ++ neg)
__device__ float g_logits[(size_t)MAXB * MAXM];      // full sim matrix (512 MB)
__device__ float g_tilemax[MAXB * 128];              // per-(row, col-tile) masked max

// ---------------- 1) normalize rows (numerics FROZEN from R11) --------------
__global__ void normalize_kernel(const float* __restrict__ anchor,
                                 const float* __restrict__ pos,
                                 const float* __restrict__ neg,
                                 int B, int Nn) {
    int r = blockIdx.x * blockDim.x + threadIdx.x;
    int total = 2 * B + Nn;
    if (r >= total) return;

    const float* src;
    float* dst;
    if (r < B)            { src = anchor + (size_t)r * BD;         dst = g_an + (size_t)r * BD; }
    else if (r < 2 * B)   { src = pos    + (size_t)(r - B) * BD;   dst = g_cn + (size_t)(r - B) * BD; }
    else                  { src = neg    + (size_t)(r - 2*B) * BD; dst = g_cn + (size_t)(r - B) * BD; }

    float x[BD];
    #pragma unroll
    for (int k = 0; k < BD; ++k) x[k] = __ldg(src + k);

    float acc0[4] = {0.f, 0.f, 0.f, 0.f};
    float acc1[4] = {0.f, 0.f, 0.f, 0.f};
    #pragma unroll
    for (int i = 0; i < 8; ++i) {
        #pragma unroll
        for (int l = 0; l < 4; ++l)
            acc0[l] = __fadd_rn(acc0[l], __fmul_rn(x[8*i + l],     x[8*i + l]));     // UNFUSED
        #pragma unroll
        for (int l = 0; l < 4; ++l)
            acc1[l] = __fadd_rn(acc1[l], __fmul_rn(x[8*i + 4 + l], x[8*i + 4 + l])); // UNFUSED
    }
    float t0 = __fadd_rn(acc0[0], acc1[0]);
    float t1 = __fadd_rn(acc0[1], acc1[1]);
    float t2 = __fadd_rn(acc0[2], acc1[2]);
    float t3 = __fadd_rn(acc0[3], acc1[3]);
    float s  = __fadd_rn(__fadd_rn(t0, t1), __fadd_rn(t2, t3));   // faddp ladder

    float den = fmaxf(__fsqrt_rn(s), 1e-8f);
    float rcp = __fdiv_rn(1.0f, den);
    #pragma unroll
    for (int k = 0; k < BD; ++k)
        dst[k] = __fmul_rn(x[k], rcp);
}

// ---------------- 2) GEMM (scalar FFMA, R11-proven) + tilemax epilogue -----
// 128x128 tile, K=64, 8x8/thread, k-ascending fused chain (bit-exact, FROZEN).
// Block also computes its rows' diagonals (exact same chain) for the mask.
__global__ void gemm_kernel(int M) {
    extern __shared__ float sm[];
    float* As    = sm;                   // [64][TS]
    float* Bs    = sm + 64 * TS;         // [64][TS]
    float* sdiag = sm + 2 * 64 * TS;     // [128]

    int t = threadIdx.x;                 // 256 threads
    int rowBase = blockIdx.y * 128;
    int colBase = blockIdx.x * 128;

    {
        const float4* A4 = reinterpret_cast<const float4*>(g_an + (size_t)rowBase * BD);
        const float4* B4 = reinterpret_cast<const float4*>(g_cn + (size_t)colBase * BD);
        #pragma unroll
        for (int it = 0; it < 8; ++it) {
            int lin = it * 256 + t;
            int r   = lin >> 4;
            int kq  = lin & 15;
            float4 va = A4[r * 16 + kq];
            float4 vb = B4[r * 16 + kq];
            int k = kq * 4;
            As[(k+0)*TS + r] = va.x; As[(k+1)*TS + r] = va.y;
            As[(k+2)*TS + r] = va.z; As[(k+3)*TS + r] = va.w;
            Bs[(k+0)*TS + r] = vb.x; Bs[(k+1)*TS + r] = vb.y;
            Bs[(k+2)*TS + r] = vb.z; Bs[(k+3)*TS + r] = vb.w;
        }
    }

    // diagonal for this row block: EXACT GEMM chain (k-ascending fused).
    // g_an/g_cn are 6 MB total -> L2-resident; redundant reads are cheap.
    if (t < 128) {
        const float* a = g_an + (size_t)(rowBase + t) * BD;
        const float* c = g_cn + (size_t)(rowBase + t) * BD;
        float s = 0.f;
        #pragma unroll
        for (int k = 0; k < BD; ++k)
            s = __fmaf_rn(a[k], c[k], s);
        sdiag[t] = s;
    }
    __syncthreads();

    int tx = t & 15, ty = t >> 4;
    int r0 = ty * 8, c0 = tx * 8;

    float acc[8][8];
    #pragma unroll
    for (int i = 0; i < 8; ++i)
        #pragma unroll
        for (int j = 0; j < 8; ++j)
            acc[i][j] = 0.f;

    #pragma unroll 8
    for (int k = 0; k < 64; ++k) {
        float4 a0 = *reinterpret_cast<const float4*>(&As[k*TS + r0]);
        float4 a1 = *reinterpret_cast<const float4*>(&As[k*TS + r0 + 4]);
        float4 b0 = *reinterpret_cast<const float4*>(&Bs[k*TS + c0]);
        float4 b1 = *reinterpret_cast<const float4*>(&Bs[k*TS + c0 + 4]);
        float a[8] = {a0.x,a0.y,a0.z,a0.w,a1.x,a1.y,a1.z,a1.w};
        float b[8] = {b0.x,b0.y,b0.z,b0.w,b1.x,b1.y,b1.z,b1.w};
        #pragma unroll
        for (int i = 0; i < 8; ++i)
            #pragma unroll
            for (int j = 0; j < 8; ++j)
                acc[i][j] = __fmaf_rn(a[i], b[j], acc[i][j]);   // fused, k-ascending
    }

    #pragma unroll
    for (int i = 0; i < 8; ++i) {
        int row = rowBase + r0 + i;
        float* Cp = g_logits + (size_t)row * M + colBase + c0;
        reinterpret_cast<float4*>(Cp)[0] = make_float4(acc[i][0], acc[i][1], acc[i][2], acc[i][3]);
        reinterpret_cast<float4*>(Cp)[1] = make_float4(acc[i][4], acc[i][5], acc[i][6], acc[i][7]);

        // masked max over this thread's 8 cols, then across the 16 tx threads
        float d = sdiag[r0 + i];
        float m = -CUDART_INF_F;
        #pragma unroll
        for (int j = 0; j < 8; ++j)
            if (acc[i][j] < d) m = fmaxf(m, acc[i][j]);
        #pragma unroll
        for (int off = 8; off; off >>= 1)
            m = fmaxf(m, __shfl_xor_sync(0xffffffffu, m, off));
        if (tx == 0)
            g_tilemax[(size_t)row * 128 + blockIdx.x] = m;   // -inf if tile empty
    }
}

// ---------------- 3) zero-fill output ----------------------------------------
__global__ void fill_kernel(float4* __restrict__ out, size_t n4) {
    size_t i = (size_t)blockIdx.x * blockDim.x + threadIdx.x;
    if (i < n4) out[i] = make_float4(0.f, 0.f, 0.f, 0.f);
}

// ---------------- 4) topk (single pass, T from tilemax) + scatter -----------
// Mask: v < diag (diag = logits[row][row], bit-exact). T = min over 128 tile
// maxima: if all tiles nonempty, >=128 masked >= T (superset of top-32);
// any empty tile -> T=-inf -> all masked survive. Selection is exact either way.
__global__ void topk_kernel(float* __restrict__ out, int B, int M) {
    int w    = (blockIdx.x * blockDim.x + threadIdx.x) >> 5;
    int lane = threadIdx.x & 31;
    if (w >= B) return;

    const float* __restrict__ Lrow = g_logits + (size_t)w * M;
    float d = Lrow[w];

    // T = min over this row's 128 tile maxima
    float4 tm = reinterpret_cast<const float4*>(g_tilemax + (size_t)w * 128)[lane];
    float T = fminf(fminf(tm.x, tm.y), fminf(tm.z, tm.w));
    #pragma unroll
    for (int off = 16; off; off >>= 1)
        T = fminf(T, __shfl_xor_sync(0xffffffffu, T, off));

    int iters = M >> 5;
    float lv[32]; int li[32];
    #pragma unroll
    for (int k = 0; k < 32; ++k) { lv[k] = -CUDART_INF_F; li[k] = 0x7FFFFFFF; }
    float curmin = -CUDART_INF_F; int minslot = 0;

    for (int i = 0; i < iters; ++i) {
        int   j = i * 32 + lane;
        float v = Lrow[j];
        if (v < d && v >= T && v > curmin) {
            lv[minslot] = v; li[minslot] = j;
            float mv = lv[0]; int mi = li[0]; int ms = 0;
            #pragma unroll
            for (int k = 1; k < 32; ++k) {
                if (lv[k] < mv || (lv[k] == mv && li[k] > mi)) { mv = lv[k]; mi = li[k]; ms = k; }
            }
            curmin = mv; minslot = ms;
        }
    }

    // merge: 32 exact warp-argmax iterations; scatter directly to out
    float bv = lv[0]; int bi = li[0]; int bslot = 0;
    #pragma unroll
    for (int k = 1; k < 32; ++k)
        if (lv[k] > bv || (lv[k] == bv && li[k] < bi)) { bv = lv[k]; bi = li[k]; bslot = k; }

    for (int it = 0; it < 32; ++it) {
        float v = bv; int idx = bi;
        #pragma unroll
        for (int off = 16; off; off >>= 1) {
            float ov = __shfl_xor_sync(0xffffffffu, v,   off);
            int   oi = __shfl_xor_sync(0xffffffffu, idx, off);
            if (ov > v || (ov == v && oi < idx)) { v = ov; idx = oi; }
        }
        if (lane == 0 && idx != 0x7FFFFFFF)
            out[(size_t)w * M + idx] = v;
        if (idx == bi && idx != 0x7FFFFFFF) {
            lv[bslot] = -CUDART_INF_F; li[bslot] = 0x7FFFFFFF;
            bv = lv[0]; bi = li[0]; bslot = 0;
            #pragma unroll
            for (int k = 1; k < 32; ++k)
                if (lv[k] > bv || (lv[k] == bv && li[k] < bi)) { bv = lv[k]; bi = li[k]; bslot = k; }
        }
    }
}

// ---------------- launcher ---------------------------------------------------
extern "C" void kernel_launch(void* const* d_in, const int* in_sizes, int n_in,
                              void* d_out, int out_size) {
    const float* anchor = (const float*)d_in[0];
    const float* pos    = (const float*)d_in[1];
    const float* neg    = (const float*)d_in[2];
    float* out = (float*)d_out;

    int B  = in_sizes[0] / BD;   // 8192
    int Nn = in_sizes[2] / BD;   // 8192
    int M  = B + Nn;             // 16384

    // #1 normalize (numerics frozen)
    int totalRows = 2 * B + Nn;
    normalize_kernel<<<(totalRows + 127) / 128, 128>>>(anchor, pos, neg, B, Nn);

    // #2 GEMM + tilemax epilogue   (6th launch overall -> ncu profiles this)
    int smemBytes = (2 * 64 * TS + 128) * (int)sizeof(float);   // 68096
    cudaFuncSetAttribute(gemm_kernel, cudaFuncAttributeMaxDynamicSharedMemorySize, smemBytes);
    dim3 ggrid(M / 128, B / 128);
    gemm_kernel<<<ggrid, 256, smemBytes>>>(M);

    // #3 zero-fill output
    size_t n4 = ((size_t)B * M) / 4;
    fill_kernel<<<(unsigned)((n4 + 255) / 256), 256>>>((float4*)out, n4);

    // #4 topk single pass + scatter
    topk_kernel<<<(B * 32 + 255) / 256, 256>>>(out, B, M);
}

// round 14
// speedup vs baseline: 1.8116x; 1.8116x over previous
#include <cuda_runtime.h>
#include <math_constants.h>

#define BD   64
#define MAXB 8192
#define MAXM 16384
#define TS   132   // smem row stride (floats) for transposed tiles

// ---------------- device scratch (static: no allocations allowed) ----------
__device__ float g_an[MAXB * BD];                    // normalized anchors
__device__ float g_cn[MAXM * BD];                    // normalized candidates (pos ++ neg)
__device__ float g_logits[(size_t)MAXB * MAXM];      // full sim matrix (512 MB)

// ---------------- 1) normalize rows (numerics FROZEN from R11) --------------
__device__ __forceinline__ void normalize_row(const float* __restrict__ src,
                                              float* __restrict__ dst) {
    float x[BD];
    #pragma unroll
    for (int k = 0; k < BD; ++k) x[k] = __ldg(src + k);

    float acc0[4] = {0.f, 0.f, 0.f, 0.f};
    float acc1[4] = {0.f, 0.f, 0.f, 0.f};
    #pragma unroll
    for (int i = 0; i < 8; ++i) {
        #pragma unroll
        for (int l = 0; l < 4; ++l)
            acc0[l] = __fadd_rn(acc0[l], __fmul_rn(x[8*i + l],     x[8*i + l]));     // UNFUSED
        #pragma unroll
        for (int l = 0; l < 4; ++l)
            acc1[l] = __fadd_rn(acc1[l], __fmul_rn(x[8*i + 4 + l], x[8*i + 4 + l])); // UNFUSED
    }
    float t0 = __fadd_rn(acc0[0], acc1[0]);
    float t1 = __fadd_rn(acc0[1], acc1[1]);
    float t2 = __fadd_rn(acc0[2], acc1[2]);
    float t3 = __fadd_rn(acc0[3], acc1[3]);
    float s  = __fadd_rn(__fadd_rn(t0, t1), __fadd_rn(t2, t3));   // faddp ladder

    float den = fmaxf(__fsqrt_rn(s), 1e-8f);
    float rcp = __fdiv_rn(1.0f, den);
    #pragma unroll
    for (int k = 0; k < BD; ++k)
        dst[k] = __fmul_rn(x[k], rcp);
}

// anchors only
__global__ void normalize_a_kernel(const float* __restrict__ anchor, int B) {
    int r = blockIdx.x * blockDim.x + threadIdx.x;
    if (r >= B) return;
    normalize_row(anchor + (size_t)r * BD, g_an + (size_t)r * BD);
}

// candidates: pos rows [0,B) then neg rows [B, B+Nn)
__global__ void normalize_c_kernel(const float* __restrict__ pos,
                                   const float* __restrict__ neg,
                                   int B, int Nn) {
    int r = blockIdx.x * blockDim.x + threadIdx.x;
    if (r >= B + Nn) return;
    const float* src = (r < B) ? pos + (size_t)r * BD : neg + (size_t)(r - B) * BD;
    normalize_row(src, g_cn + (size_t)r * BD);
}

// ---------------- 2) zero-fill output (launch #3) ---------------------------
__global__ void fill_kernel(float4* __restrict__ out, size_t n4) {
    size_t i = (size_t)blockIdx.x * blockDim.x + threadIdx.x;
    if (i < n4) out[i] = make_float4(0.f, 0.f, 0.f, 0.f);
}

// ---------------- 3) GEMM (launch #4 -> ncu target) -------------------------
// 128x128 tile, K=64, 8x8/thread, k-ascending fused chain (bit-exact, FROZEN).
// No staging arrays: direct float4-component FMAs.
__global__ __launch_bounds__(256, 2) void gemm_kernel(int M) {
    extern __shared__ float sm[];
    float* As = sm;                 // [64][TS] transposed: As[k*TS + m]
    float* Bs = sm + 64 * TS;       // [64][TS] transposed: Bs[k*TS + n]

    int t = threadIdx.x;            // 256 threads
    int rowBase = blockIdx.y * 128;
    int colBase = blockIdx.x * 128;

    {
        const float4* A4 = reinterpret_cast<const float4*>(g_an + (size_t)rowBase * BD);
        const float4* B4 = reinterpret_cast<const float4*>(g_cn + (size_t)colBase * BD);
        #pragma unroll
        for (int it = 0; it < 8; ++it) {
            int lin = it * 256 + t;
            int r   = lin >> 4;
            int kq  = lin & 15;
            float4 va = A4[r * 16 + kq];
            float4 vb = B4[r * 16 + kq];
            int k = kq * 4;
            As[(k+0)*TS + r] = va.x; As[(k+1)*TS + r] = va.y;
            As[(k+2)*TS + r] = va.z; As[(k+3)*TS + r] = va.w;
            Bs[(k+0)*TS + r] = vb.x; Bs[(k+1)*TS + r] = vb.y;
            Bs[(k+2)*TS + r] = vb.z; Bs[(k+3)*TS + r] = vb.w;
        }
    }
    __syncthreads();

    int tx = t & 15, ty = t >> 4;
    int r0 = ty * 8, c0 = tx * 8;

    float acc[8][8];
    #pragma unroll
    for (int i = 0; i < 8; ++i)
        #pragma unroll
        for (int j = 0; j < 8; ++j)
            acc[i][j] = 0.f;

    #pragma unroll 4
    for (int k = 0; k < 64; ++k) {
        float4 a0 = *reinterpret_cast<const float4*>(&As[k*TS + r0]);
        float4 a1 = *reinterpret_cast<const float4*>(&As[k*TS + r0 + 4]);
        float4 b0 = *reinterpret_cast<const float4*>(&Bs[k*TS + c0]);
        float4 b1 = *reinterpret_cast<const float4*>(&Bs[k*TS + c0 + 4]);

        #define ROW_FMA(i, av)                                   \
            acc[i][0] = __fmaf_rn(av, b0.x, acc[i][0]);          \
            acc[i][1] = __fmaf_rn(av, b0.y, acc[i][1]);          \
            acc[i][2] = __fmaf_rn(av, b0.z, acc[i][2]);          \
            acc[i][3] = __fmaf_rn(av, b0.w, acc[i][3]);          \
            acc[i][4] = __fmaf_rn(av, b1.x, acc[i][4]);          \
            acc[i][5] = __fmaf_rn(av, b1.y, acc[i][5]);          \
            acc[i][6] = __fmaf_rn(av, b1.z, acc[i][6]);          \
            acc[i][7] = __fmaf_rn(av, b1.w, acc[i][7]);
        ROW_FMA(0, a0.x) ROW_FMA(1, a0.y) ROW_FMA(2, a0.z) ROW_FMA(3, a0.w)
        ROW_FMA(4, a1.x) ROW_FMA(5, a1.y) ROW_FMA(6, a1.z) ROW_FMA(7, a1.w)
        #undef ROW_FMA
    }

    #pragma unroll
    for (int i = 0; i < 8; ++i) {
        float* Cp = g_logits + (size_t)(rowBase + r0 + i) * M + colBase + c0;
        reinterpret_cast<float4*>(Cp)[0] = make_float4(acc[i][0], acc[i][1], acc[i][2], acc[i][3]);
        reinterpret_cast<float4*>(Cp)[1] = make_float4(acc[i][4], acc[i][5], acc[i][6], acc[i][7]);
    }
}

// ---------------- 4) topk (2-pass, R11-proven) + direct scatter -------------
__global__ void topk_kernel(float* __restrict__ out, int B, int M) {
    int w    = (blockIdx.x * blockDim.x + threadIdx.x) >> 5;
    int lane = threadIdx.x & 31;
    if (w >= B) return;

    const float* __restrict__ Lrow = g_logits + (size_t)w * M;
    float d = Lrow[w];
    int iters = M >> 5;

    // pass 1: T = warp-min of per-lane masked maxima (>=32 masked >= T)
    float mmax = -CUDART_INF_F;
    for (int i = 0; i < iters; ++i) {
        float v = Lrow[i * 32 + lane];
        if (v < d) mmax = fmaxf(mmax, v);
    }
    float T = mmax;
    #pragma unroll
    for (int off = 16; off; off >>= 1)
        T = fminf(T, __shfl_xor_sync(0xffffffffu, T, off));

    // pass 2: per-lane top-32 list over survivors (v<d && v>=T)
    float lv[32]; int li[32];
    #pragma unroll
    for (int k = 0; k < 32; ++k) { lv[k] = -CUDART_INF_F; li[k] = 0x7FFFFFFF; }
    float curmin = -CUDART_INF_F; int minslot = 0;

    for (int i = 0; i < iters; ++i) {
        int   j = i * 32 + lane;
        float v = Lrow[j];
        if (v < d && v >= T && v > curmin) {
            lv[minslot] = v; li[minslot] = j;
            float mv = lv[0]; int mi = li[0]; int ms = 0;
            #pragma unroll
            for (int k = 1; k < 32; ++k) {
                if (lv[k] < mv || (lv[k] == mv && li[k] > mi)) { mv = lv[k]; mi = li[k]; ms = k; }
            }
            curmin = mv; minslot = ms;
        }
    }

    // merge: 32 exact warp-argmax iterations; lane 0 writes out directly
    float bv = lv[0]; int bi = li[0]; int bslot = 0;
    #pragma unroll
    for (int k = 1; k < 32; ++k)
        if (lv[k] > bv || (lv[k] == bv && li[k] < bi)) { bv = lv[k]; bi = li[k]; bslot = k; }

    for (int it = 0; it < 32; ++it) {
        float v = bv; int idx = bi;
        #pragma unroll
        for (int off = 16; off; off >>= 1) {
            float ov = __shfl_xor_sync(0xffffffffu, v,   off);
            int   oi = __shfl_xor_sync(0xffffffffu, idx, off);
            if (ov > v || (ov == v && oi < idx)) { v = ov; idx = oi; }
        }
        if (lane == 0 && idx != 0x7FFFFFFF)
            out[(size_t)w * M + idx] = v;
        if (idx == bi && idx != 0x7FFFFFFF) {
            lv[bslot] = -CUDART_INF_F; li[bslot] = 0x7FFFFFFF;
            bv = lv[0]; bi = li[0]; bslot = 0;
            #pragma unroll
            for (int k = 1; k < 32; ++k)
                if (lv[k] > bv || (lv[k] == bv && li[k] < bi)) { bv = lv[k]; bi = li[k]; bslot = k; }
        }
    }
}

// ---------------- launcher ---------------------------------------------------
extern "C" void kernel_launch(void* const* d_in, const int* in_sizes, int n_in,
                              void* d_out, int out_size) {
    const float* anchor = (const float*)d_in[0];
    const float* pos    = (const float*)d_in[1];
    const float* neg    = (const float*)d_in[2];
    float* out = (float*)d_out;

    int B  = in_sizes[0] / BD;   // 8192
    int Nn = in_sizes[2] / BD;   // 8192
    int M  = B + Nn;             // 16384

    // #1 normalize anchors
    normalize_a_kernel<<<(B + 127) / 128, 128>>>(anchor, B);

    // #2 normalize candidates
    normalize_c_kernel<<<(B + Nn + 127) / 128, 128>>>(pos, neg, B, Nn);

    // #3 zero-fill output (independent; ordered before topk by the stream)
    size_t n4 = ((size_t)B * M) / 4;
    fill_kernel<<<(unsigned)((n4 + 255) / 256), 256>>>((float4*)out, n4);

    // #4 GEMM  <-- ncu profiles the 4th launch
    int smemBytes = 2 * 64 * TS * (int)sizeof(float);   // 67584
    cudaFuncSetAttribute(gemm_kernel, cudaFuncAttributeMaxDynamicSharedMemorySize, smemBytes);
    dim3 ggrid(M / 128, B / 128);
    gemm_kernel<<<ggrid, 256, smemBytes>>>(M);

    // #5 topk (2-pass) + direct scatter
    topk_kernel<<<(B * 32 + 255) / 256, 256>>>(out, B, M);
}

// round 15
// speedup vs baseline: 3.3552x; 1.8521x over previous
#include <cuda_runtime.h>
#include <math_constants.h>

#define BD   64
#define MAXB 8192
#define MAXM 16384
#define TS   132     // smem row stride (floats) for transposed tiles
#define TKC  1024    // per-warp survivor buffer capacity

// ---------------- device scratch (static: no allocations allowed) ----------
__device__ float g_an[MAXB * BD];                    // normalized anchors
__device__ float g_cn[MAXM * BD];                    // normalized candidates (pos ++ neg)
__device__ float g_logits[(size_t)MAXB * MAXM];      // full sim matrix (512 MB)

// ---------------- 1) zero-fill output (launch #1, independent) -------------
__global__ void fill_kernel(float4* __restrict__ out, size_t n4) {
    size_t i = (size_t)blockIdx.x * blockDim.x + threadIdx.x;
    if (i < n4) out[i] = make_float4(0.f, 0.f, 0.f, 0.f);
}

// ---------------- 2) normalize rows (numerics FROZEN from R11) --------------
__global__ void normalize_kernel(const float* __restrict__ anchor,
                                 const float* __restrict__ pos,
                                 const float* __restrict__ neg,
                                 int B, int Nn) {
    int r = blockIdx.x * blockDim.x + threadIdx.x;
    int total = 2 * B + Nn;
    if (r >= total) return;

    const float* src;
    float* dst;
    if (r < B)            { src = anchor + (size_t)r * BD;         dst = g_an + (size_t)r * BD; }
    else if (r < 2 * B)   { src = pos    + (size_t)(r - B) * BD;   dst = g_cn + (size_t)(r - B) * BD; }
    else                  { src = neg    + (size_t)(r - 2*B) * BD; dst = g_cn + (size_t)(r - B) * BD; }

    float x[BD];
    #pragma unroll
    for (int k = 0; k < BD; ++k) x[k] = __ldg(src + k);

    float acc0[4] = {0.f, 0.f, 0.f, 0.f};
    float acc1[4] = {0.f, 0.f, 0.f, 0.f};
    #pragma unroll
    for (int i = 0; i < 8; ++i) {
        #pragma unroll
        for (int l = 0; l < 4; ++l)
            acc0[l] = __fadd_rn(acc0[l], __fmul_rn(x[8*i + l],     x[8*i + l]));     // UNFUSED
        #pragma unroll
        for (int l = 0; l < 4; ++l)
            acc1[l] = __fadd_rn(acc1[l], __fmul_rn(x[8*i + 4 + l], x[8*i + 4 + l])); // UNFUSED
    }
    float t0 = __fadd_rn(acc0[0], acc1[0]);
    float t1 = __fadd_rn(acc0[1], acc1[1]);
    float t2 = __fadd_rn(acc0[2], acc1[2]);
    float t3 = __fadd_rn(acc0[3], acc1[3]);
    float s  = __fadd_rn(__fadd_rn(t0, t1), __fadd_rn(t2, t3));   // faddp ladder

    float den = fmaxf(__fsqrt_rn(s), 1e-8f);
    float rcp = __fdiv_rn(1.0f, den);
    #pragma unroll
    for (int k = 0; k < BD; ++k)
        dst[k] = __fmul_rn(x[k], rcp);
}

// ---------------- 3) GEMM (launch #3; bit-exact chain FROZEN) ---------------
__global__ __launch_bounds__(256, 2) void gemm_kernel(int M) {
    extern __shared__ float sm[];
    float* As = sm;                 // [64][TS]
    float* Bs = sm + 64 * TS;       // [64][TS]

    int t = threadIdx.x;            // 256 threads
    int rowBase = blockIdx.y * 128;
    int colBase = blockIdx.x * 128;

    {
        const float4* A4 = reinterpret_cast<const float4*>(g_an + (size_t)rowBase * BD);
        const float4* B4 = reinterpret_cast<const float4*>(g_cn + (size_t)colBase * BD);
        #pragma unroll
        for (int it = 0; it < 8; ++it) {
            int lin = it * 256 + t;
            int r   = lin >> 4;
            int kq  = lin & 15;
            float4 va = A4[r * 16 + kq];
            float4 vb = B4[r * 16 + kq];
            int k = kq * 4;
            As[(k+0)*TS + r] = va.x; As[(k+1)*TS + r] = va.y;
            As[(k+2)*TS + r] = va.z; As[(k+3)*TS + r] = va.w;
            Bs[(k+0)*TS + r] = vb.x; Bs[(k+1)*TS + r] = vb.y;
            Bs[(k+2)*TS + r] = vb.z; Bs[(k+3)*TS + r] = vb.w;
        }
    }
    __syncthreads();

    int tx = t & 15, ty = t >> 4;
    int r0 = ty * 8, c0 = tx * 8;

    float acc[8][8];
    #pragma unroll
    for (int i = 0; i < 8; ++i)
        #pragma unroll
        for (int j = 0; j < 8; ++j)
            acc[i][j] = 0.f;

    #pragma unroll 4
    for (int k = 0; k < 64; ++k) {
        float4 a0 = *reinterpret_cast<const float4*>(&As[k*TS + r0]);
        float4 a1 = *reinterpret_cast<const float4*>(&As[k*TS + r0 + 4]);
        float4 b0 = *reinterpret_cast<const float4*>(&Bs[k*TS + c0]);
        float4 b1 = *reinterpret_cast<const float4*>(&Bs[k*TS + c0 + 4]);

        #define ROW_FMA(i, av)                                   \
            acc[i][0] = __fmaf_rn(av, b0.x, acc[i][0]);          \
            acc[i][1] = __fmaf_rn(av, b0.y, acc[i][1]);          \
            acc[i][2] = __fmaf_rn(av, b0.z, acc[i][2]);          \
            acc[i][3] = __fmaf_rn(av, b0.w, acc[i][3]);          \
            acc[i][4] = __fmaf_rn(av, b1.x, acc[i][4]);          \
            acc[i][5] = __fmaf_rn(av, b1.y, acc[i][5]);          \
            acc[i][6] = __fmaf_rn(av, b1.z, acc[i][6]);          \
            acc[i][7] = __fmaf_rn(av, b1.w, acc[i][7]);
        ROW_FMA(0, a0.x) ROW_FMA(1, a0.y) ROW_FMA(2, a0.z) ROW_FMA(3, a0.w)
        ROW_FMA(4, a1.x) ROW_FMA(5, a1.y) ROW_FMA(6, a1.z) ROW_FMA(7, a1.w)
        #undef ROW_FMA
    }

    #pragma unroll
    for (int i = 0; i < 8; ++i) {
        float* Cp = g_logits + (size_t)(rowBase + r0 + i) * M + colBase + c0;
        reinterpret_cast<float4*>(Cp)[0] = make_float4(acc[i][0], acc[i][1], acc[i][2], acc[i][3]);
        reinterpret_cast<float4*>(Cp)[1] = make_float4(acc[i][4], acc[i][5], acc[i][6], acc[i][7]);
    }
}

// ---------------- 4) topk: compaction-based (launch #4 -> ncu target) -------
// Warp per row. Pass 1: T = warp-min of per-lane masked maxima (float4 groups;
// any 32-partition keeps the ">=32 masked >= T" guarantee). Pass 2: ballot-
// compact survivors into smem. Selection: 32 exact warp-argmax rounds
// (value desc, lowest index wins ties), lane 0 scatters into out.
// Overflow (cnt > TKC) -> exact R11 insertion fallback (never expected).
__global__ void topk_kernel(float* __restrict__ out, int B, int M) {
    extern __shared__ float smem[];
    int wl   = threadIdx.x >> 5;                  // warp within block
    int w    = (blockIdx.x * blockDim.x + threadIdx.x) >> 5;
    int lane = threadIdx.x & 31;
    if (w >= B) return;

    float* sv = smem + (size_t)wl * TKC;          // values
    int*   si = (int*)(smem + 8 * TKC) + (size_t)wl * TKC;   // indices

    const float* __restrict__ Lrow = g_logits + (size_t)w * M;
    const float4* __restrict__ L4  = reinterpret_cast<const float4*>(Lrow);
    float d = Lrow[w];
    int q4 = M >> 2;                              // 4096 float4s

    // ---- pass 1: threshold ----
    float mmax = -CUDART_INF_F;
    #pragma unroll 4
    for (int i = lane; i < q4; i += 32) {
        float4 v = L4[i];
        if (v.x < d) mmax = fmaxf(mmax, v.x);
        if (v.y < d) mmax = fmaxf(mmax, v.y);
        if (v.z < d) mmax = fmaxf(mmax, v.z);
        if (v.w < d) mmax = fmaxf(mmax, v.w);
    }
    float T = mmax;
    #pragma unroll
    for (int off = 16; off; off >>= 1)
        T = fminf(T, __shfl_xor_sync(0xffffffffu, T, off));

    // ---- pass 2: ballot compaction ----
    int cnt = 0;
    #pragma unroll 2
    for (int i = lane; i < q4; i += 32) {
        float4 v = L4[i];
        int jb = i << 2;
        #define COMPACT(val, joff) {                                          \
            bool keep = ((val) < d) && ((val) >= T);                          \
            unsigned mask = __ballot_sync(0xffffffffu, keep);                 \
            if (keep) {                                                       \
                int pos = cnt + __popc(mask & ((1u << lane) - 1u));           \
                if (pos < TKC) { sv[pos] = (val); si[pos] = jb + (joff); }    \
            }                                                                 \
            cnt += __popc(mask);                                              \
        }
        COMPACT(v.x, 0) COMPACT(v.y, 1) COMPACT(v.z, 2) COMPACT(v.w, 3)
        #undef COMPACT
    }
    __syncwarp();

    if (cnt <= TKC) {
        // ---- selection: 32 exact argmax rounds over cnt survivors ----
        for (int it = 0; it < 32; ++it) {
            float bv = -CUDART_INF_F; int bidx = 0x7FFFFFFF; int bslot = -1;
            for (int s = lane; s < cnt; s += 32) {
                float v = sv[s]; int ix = si[s];
                if (v > bv || (v == bv && ix < bidx)) { bv = v; bidx = ix; bslot = s; }
            }
            #pragma unroll
            for (int off = 16; off; off >>= 1) {
                float ov = __shfl_xor_sync(0xffffffffu, bv,    off);
                int   oi = __shfl_xor_sync(0xffffffffu, bidx,  off);
                int   os = __shfl_xor_sync(0xffffffffu, bslot, off);
                if (ov > bv || (ov == bv && oi < bidx)) { bv = ov; bidx = oi; bslot = os; }
            }
            if (bidx == 0x7FFFFFFF) break;        // fewer than 32 survivors
            if (lane == 0) {
                out[(size_t)w * M + bidx] = bv;
                sv[bslot] = -CUDART_INF_F;        // remove winner
                si[bslot] = 0x7FFFFFFF;
            }
            __syncwarp();
        }
    } else {
        // ---- overflow fallback: exact R11 insertion path ----
        float lv[32]; int li[32];
        #pragma unroll
        for (int k = 0; k < 32; ++k) { lv[k] = -CUDART_INF_F; li[k] = 0x7FFFFFFF; }
        float curmin = -CUDART_INF_F; int minslot = 0;
        int iters = M >> 5;
        for (int i = 0; i < iters; ++i) {
            int   j = i * 32 + lane;
            float v = Lrow[j];
            if (v < d && v >= T && v > curmin) {
                lv[minslot] = v; li[minslot] = j;
                float mv = lv[0]; int mi = li[0]; int ms = 0;
                #pragma unroll
                for (int k = 1; k < 32; ++k)
                    if (lv[k] < mv || (lv[k] == mv && li[k] > mi)) { mv = lv[k]; mi = li[k]; ms = k; }
                curmin = mv; minslot = ms;
            }
        }
        float bv = lv[0]; int bi = li[0]; int bslot = 0;
        #pragma unroll
        for (int k = 1; k < 32; ++k)
            if (lv[k] > bv || (lv[k] == bv && li[k] < bi)) { bv = lv[k]; bi = li[k]; bslot = k; }
        for (int it = 0; it < 32; ++it) {
            float v = bv; int idx = bi;
            #pragma unroll
            for (int off = 16; off; off >>= 1) {
                float ov = __shfl_xor_sync(0xffffffffu, v,   off);
                int   oi = __shfl_xor_sync(0xffffffffu, idx, off);
                if (ov > v || (ov == v && oi < idx)) { v = ov; idx = oi; }
            }
            if (lane == 0 && idx != 0x7FFFFFFF)
                out[(size_t)w * M + idx] = v;
            if (idx == bi && idx != 0x7FFFFFFF) {
                lv[bslot] = -CUDART_INF_F; li[bslot] = 0x7FFFFFFF;
                bv = lv[0]; bi = li[0]; bslot = 0;
                #pragma unroll
                for (int k = 1; k < 32; ++k)
                    if (lv[k] > bv || (lv[k] == bv && li[k] < bi)) { bv = lv[k]; bi = li[k]; bslot = k; }
            }
        }
    }
}

// ---------------- launcher ---------------------------------------------------
extern "C" void kernel_launch(void* const* d_in, const int* in_sizes, int n_in,
                              void* d_out, int out_size) {
    const float* anchor = (const float*)d_in[0];
    const float* pos    = (const float*)d_in[1];
    const float* neg    = (const float*)d_in[2];
    float* out = (float*)d_out;

    int B  = in_sizes[0] / BD;   // 8192
    int Nn = in_sizes[2] / BD;   // 8192
    int M  = B + Nn;             // 16384

    // #1 zero-fill output (independent)
    size_t n4 = ((size_t)B * M) / 4;
    fill_kernel<<<(unsigned)((n4 + 255) / 256), 256>>>((float4*)out, n4);

    // #2 normalize (numerics frozen)
    int totalRows = 2 * B + Nn;
    normalize_kernel<<<(totalRows + 127) / 128, 128>>>(anchor, pos, neg, B, Nn);

    // #3 GEMM
    int smemBytes = 2 * 64 * TS * (int)sizeof(float);   // 67584
    cudaFuncSetAttribute(gemm_kernel, cudaFuncAttributeMaxDynamicSharedMemorySize, smemBytes);
    dim3 ggrid(M / 128, B / 128);
    gemm_kernel<<<ggrid, 256, smemBytes>>>(M);

    // #4 topk (compaction) + direct scatter   <-- ncu profiles launch #4
    int tkSmem = 8 * TKC * 2 * (int)sizeof(float);      // 64 KB
    cudaFuncSetAttribute(topk_kernel, cudaFuncAttributeMaxDynamicSharedMemorySize, tkSmem);
    topk_kernel<<<(B * 32 + 255) / 256, 256, tkSmem>>>(out, B, M);
}

// round 16
// speedup vs baseline: 3.5634x; 1.0621x over previous
#include <cuda_runtime.h>
#include <math_constants.h>

#define BD   64
#define MAXB 8192
#define MAXM 16384
#define TS   132     // smem row stride (floats) for transposed tiles
#define TKC  512     // per-warp survivor buffer capacity

// ---------------- device scratch (static: no allocations allowed) ----------
__device__ float g_an[MAXB * BD];                    // normalized anchors
__device__ float g_cn[MAXM * BD];                    // normalized candidates (pos ++ neg)
__device__ float g_logits[(size_t)MAXB * MAXM];      // full sim matrix (512 MB)

// ---------------- 1) zero-fill output (launch #1, independent) -------------
__global__ void fill_kernel(float4* __restrict__ out, size_t n4) {
    size_t i = (size_t)blockIdx.x * blockDim.x + threadIdx.x;
    if (i < n4) out[i] = make_float4(0.f, 0.f, 0.f, 0.f);
}

// ---------------- 2) normalize rows (numerics FROZEN from R11) --------------
__global__ void normalize_kernel(const float* __restrict__ anchor,
                                 const float* __restrict__ pos,
                                 const float* __restrict__ neg,
                                 int B, int Nn) {
    int r = blockIdx.x * blockDim.x + threadIdx.x;
    int total = 2 * B + Nn;
    if (r >= total) return;

    const float* src;
    float* dst;
    if (r < B)            { src = anchor + (size_t)r * BD;         dst = g_an + (size_t)r * BD; }
    else if (r < 2 * B)   { src = pos    + (size_t)(r - B) * BD;   dst = g_cn + (size_t)(r - B) * BD; }
    else                  { src = neg    + (size_t)(r - 2*B) * BD; dst = g_cn + (size_t)(r - B) * BD; }

    float x[BD];
    #pragma unroll
    for (int k = 0; k < BD; ++k) x[k] = __ldg(src + k);

    float acc0[4] = {0.f, 0.f, 0.f, 0.f};
    float acc1[4] = {0.f, 0.f, 0.f, 0.f};
    #pragma unroll
    for (int i = 0; i < 8; ++i) {
        #pragma unroll
        for (int l = 0; l < 4; ++l)
            acc0[l] = __fadd_rn(acc0[l], __fmul_rn(x[8*i + l],     x[8*i + l]));     // UNFUSED
        #pragma unroll
        for (int l = 0; l < 4; ++l)
            acc1[l] = __fadd_rn(acc1[l], __fmul_rn(x[8*i + 4 + l], x[8*i + 4 + l])); // UNFUSED
    }
    float t0 = __fadd_rn(acc0[0], acc1[0]);
    float t1 = __fadd_rn(acc0[1], acc1[1]);
    float t2 = __fadd_rn(acc0[2], acc1[2]);
    float t3 = __fadd_rn(acc0[3], acc1[3]);
    float s  = __fadd_rn(__fadd_rn(t0, t1), __fadd_rn(t2, t3));   // faddp ladder

    float den = fmaxf(__fsqrt_rn(s), 1e-8f);
    float rcp = __fdiv_rn(1.0f, den);
    #pragma unroll
    for (int k = 0; k < BD; ++k)
        dst[k] = __fmul_rn(x[k], rcp);
}

// ---------------- 3) GEMM (bit-exact chain FROZEN; at FFMA roofline) --------
__global__ __launch_bounds__(256, 2) void gemm_kernel(int M) {
    extern __shared__ float sm[];
    float* As = sm;                 // [64][TS]
    float* Bs = sm + 64 * TS;       // [64][TS]

    int t = threadIdx.x;            // 256 threads
    int rowBase = blockIdx.y * 128;
    int colBase = blockIdx.x * 128;

    {
        const float4* A4 = reinterpret_cast<const float4*>(g_an + (size_t)rowBase * BD);
        const float4* B4 = reinterpret_cast<const float4*>(g_cn + (size_t)colBase * BD);
        #pragma unroll
        for (int it = 0; it < 8; ++it) {
            int lin = it * 256 + t;
            int r   = lin >> 4;
            int kq  = lin & 15;
            float4 va = A4[r * 16 + kq];
            float4 vb = B4[r * 16 + kq];
            int k = kq * 4;
            As[(k+0)*TS + r] = va.x; As[(k+1)*TS + r] = va.y;
            As[(k+2)*TS + r] = va.z; As[(k+3)*TS + r] = va.w;
            Bs[(k+0)*TS + r] = vb.x; Bs[(k+1)*TS + r] = vb.y;
            Bs[(k+2)*TS + r] = vb.z; Bs[(k+3)*TS + r] = vb.w;
        }
    }
    __syncthreads();

    int tx = t & 15, ty = t >> 4;
    int r0 = ty * 8, c0 = tx * 8;

    float acc[8][8];
    #pragma unroll
    for (int i = 0; i < 8; ++i)
        #pragma unroll
        for (int j = 0; j < 8; ++j)
            acc[i][j] = 0.f;

    #pragma unroll 4
    for (int k = 0; k < 64; ++k) {
        float4 a0 = *reinterpret_cast<const float4*>(&As[k*TS + r0]);
        float4 a1 = *reinterpret_cast<const float4*>(&As[k*TS + r0 + 4]);
        float4 b0 = *reinterpret_cast<const float4*>(&Bs[k*TS + c0]);
        float4 b1 = *reinterpret_cast<const float4*>(&Bs[k*TS + c0 + 4]);

        #define ROW_FMA(i, av)                                   \
            acc[i][0] = __fmaf_rn(av, b0.x, acc[i][0]);          \
            acc[i][1] = __fmaf_rn(av, b0.y, acc[i][1]);          \
            acc[i][2] = __fmaf_rn(av, b0.z, acc[i][2]);          \
            acc[i][3] = __fmaf_rn(av, b0.w, acc[i][3]);          \
            acc[i][4] = __fmaf_rn(av, b1.x, acc[i][4]);          \
            acc[i][5] = __fmaf_rn(av, b1.y, acc[i][5]);          \
            acc[i][6] = __fmaf_rn(av, b1.z, acc[i][6]);          \
            acc[i][7] = __fmaf_rn(av, b1.w, acc[i][7]);
        ROW_FMA(0, a0.x) ROW_FMA(1, a0.y) ROW_FMA(2, a0.z) ROW_FMA(3, a0.w)
        ROW_FMA(4, a1.x) ROW_FMA(5, a1.y) ROW_FMA(6, a1.z) ROW_FMA(7, a1.w)
        #undef ROW_FMA
    }

    #pragma unroll
    for (int i = 0; i < 8; ++i) {
        float* Cp = g_logits + (size_t)(rowBase + r0 + i) * M + colBase + c0;
        reinterpret_cast<float4*>(Cp)[0] = make_float4(acc[i][0], acc[i][1], acc[i][2], acc[i][3]);
        reinterpret_cast<float4*>(Cp)[1] = make_float4(acc[i][4], acc[i][5], acc[i][6], acc[i][7]);
    }
}

// ---------------- 4) topk: compaction, reg-light (launch #4 -> ncu) ---------
// Warp per row, 2 passes. Overflow fallback = exact lexicographic descent
// straight from gmem (no big register arrays -> high occupancy main path).
__global__ __launch_bounds__(256, 5) void topk_kernel(float* __restrict__ out, int B, int M) {
    extern __shared__ float smem[];
    int wl   = threadIdx.x >> 5;
    int w    = (blockIdx.x * blockDim.x + threadIdx.x) >> 5;
    int lane = threadIdx.x & 31;
    if (w >= B) return;

    float* sv = smem + (size_t)wl * TKC;                      // values
    int*   si = (int*)(smem + 8 * TKC) + (size_t)wl * TKC;    // indices

    const float* __restrict__ Lrow = g_logits + (size_t)w * M;
    const float4* __restrict__ L4  = reinterpret_cast<const float4*>(Lrow);
    float d = Lrow[w];
    int q4 = M >> 2;                              // 4096 float4s

    // ---- pass 1: T = warp-min of per-lane masked maxima ----
    float mmax = -CUDART_INF_F;
    #pragma unroll 8
    for (int i = lane; i < q4; i += 32) {
        float4 v = L4[i];
        if (v.x < d) mmax = fmaxf(mmax, v.x);
        if (v.y < d) mmax = fmaxf(mmax, v.y);
        if (v.z < d) mmax = fmaxf(mmax, v.z);
        if (v.w < d) mmax = fmaxf(mmax, v.w);
    }
    float T = mmax;
    #pragma unroll
    for (int off = 16; off; off >>= 1)
        T = fminf(T, __shfl_xor_sync(0xffffffffu, T, off));

    // ---- pass 2: ballot compaction of survivors ----
    int cnt = 0;
    #pragma unroll 4
    for (int i = lane; i < q4; i += 32) {
        float4 v = L4[i];
        int jb = i << 2;
        #define COMPACT(val, joff) {                                          \
            bool keep = ((val) < d) && ((val) >= T);                          \
            unsigned mask = __ballot_sync(0xffffffffu, keep);                 \
            if (keep) {                                                       \
                int pos = cnt + __popc(mask & ((1u << lane) - 1u));           \
                if (pos < TKC) { sv[pos] = (val); si[pos] = jb + (joff); }    \
            }                                                                 \
            cnt += __popc(mask);                                              \
        }
        COMPACT(v.x, 0) COMPACT(v.y, 1) COMPACT(v.z, 2) COMPACT(v.w, 3)
        #undef COMPACT
    }
    __syncwarp();

    if (cnt <= TKC) {
        // ---- selection: 32 exact argmax rounds over survivors ----
        for (int it = 0; it < 32; ++it) {
            float bv = -CUDART_INF_F; int bidx = 0x7FFFFFFF; int bslot = -1;
            for (int s = lane; s < cnt; s += 32) {
                float v = sv[s]; int ix = si[s];
                if (v > bv || (v == bv && ix < bidx)) { bv = v; bidx = ix; bslot = s; }
            }
            #pragma unroll
            for (int off = 16; off; off >>= 1) {
                float ov = __shfl_xor_sync(0xffffffffu, bv,    off);
                int   oi = __shfl_xor_sync(0xffffffffu, bidx,  off);
                int   os = __shfl_xor_sync(0xffffffffu, bslot, off);
                if (ov > bv || (ov == bv && oi < bidx)) { bv = ov; bidx = oi; bslot = os; }
            }
            if (bidx == 0x7FFFFFFF) break;
            if (lane == 0) {
                out[(size_t)w * M + bidx] = bv;
                sv[bslot] = -CUDART_INF_F;
                si[bslot] = 0x7FFFFFFF;
            }
            __syncwarp();
        }
    } else {
        // ---- ultra-rare exact fallback: lexicographic descent from gmem ----
        // Order: value desc, index asc. Each round finds the next (v,idx).
        float pv = CUDART_INF_F; int pi = -1;
        for (int it = 0; it < 32; ++it) {
            float bv = -CUDART_INF_F; int bidx = 0x7FFFFFFF;
            for (int i = lane; i < M; i += 32) {
                float v = Lrow[i];
                if (v >= d) continue;                       // mask
                bool after = (v < pv) || (v == pv && i > pi);
                if (!after) continue;
                if (v > bv || (v == bv && i < bidx)) { bv = v; bidx = i; }
            }
            #pragma unroll
            for (int off = 16; off; off >>= 1) {
                float ov = __shfl_xor_sync(0xffffffffu, bv,   off);
                int   oi = __shfl_xor_sync(0xffffffffu, bidx, off);
                if (ov > bv || (ov == bv && oi < bidx)) { bv = ov; bidx = oi; }
            }
            if (bidx == 0x7FFFFFFF) break;
            if (lane == 0) out[(size_t)w * M + bidx] = bv;
            pv = bv; pi = bidx;
        }
    }
}

// ---------------- launcher ---------------------------------------------------
extern "C" void kernel_launch(void* const* d_in, const int* in_sizes, int n_in,
                              void* d_out, int out_size) {
    const float* anchor = (const float*)d_in[0];
    const float* pos    = (const float*)d_in[1];
    const float* neg    = (const float*)d_in[2];
    float* out = (float*)d_out;

    int B  = in_sizes[0] / BD;   // 8192
    int Nn = in_sizes[2] / BD;   // 8192
    int M  = B + Nn;             // 16384

    // #1 zero-fill output (independent)
    size_t n4 = ((size_t)B * M) / 4;
    fill_kernel<<<(unsigned)((n4 + 255) / 256), 256>>>((float4*)out, n4);

    // #2 normalize (numerics frozen)
    int totalRows = 2 * B + Nn;
    normalize_kernel<<<(totalRows + 127) / 128, 128>>>(anchor, pos, neg, B, Nn);

    // #3 GEMM
    int smemBytes = 2 * 64 * TS * (int)sizeof(float);   // 67584
    cudaFuncSetAttribute(gemm_kernel, cudaFuncAttributeMaxDynamicSharedMemorySize, smemBytes);
    dim3 ggrid(M / 128, B / 128);
    gemm_kernel<<<ggrid, 256, smemBytes>>>(M);

    // #4 topk (compaction, high-occupancy) + direct scatter
    int tkSmem = 8 * TKC * 2 * (int)sizeof(float);      // 32 KB
    cudaFuncSetAttribute(topk_kernel, cudaFuncAttributeMaxDynamicSharedMemorySize, tkSmem);
    topk_kernel<<<(B * 32 + 255) / 256, 256, tkSmem>>>(out, B, M);
}

// round 17
// speedup vs baseline: 3.7875x; 1.0629x over previous
#include <cuda_runtime.h>
#include <math_constants.h>

#define BD   64
#define MAXB 8192
#define MAXM 16384
#define TS   132     // smem row stride (floats) for transposed tiles
#define TKC  512     // per-warp survivor buffer capacity

// ---------------- device scratch (static: no allocations allowed) ----------
__device__ float g_an[MAXB * BD];                    // normalized anchors
__device__ float g_cn[MAXM * BD];                    // normalized candidates (pos ++ neg)
__device__ float g_logits[(size_t)MAXB * MAXM];      // full sim matrix (512 MB)
__device__ float g_diag[MAXB];                       // diagonal (bit-identical chain)
__device__ float g_tilemax[MAXB * 128];              // per-(row, col-tile) masked max

// ---------------- 1) normalize rows (numerics FROZEN from R11) --------------
__global__ void normalize_kernel(const float* __restrict__ anchor,
                                 const float* __restrict__ pos,
                                 const float* __restrict__ neg,
                                 int B, int Nn) {
    int r = blockIdx.x * blockDim.x + threadIdx.x;
    int total = 2 * B + Nn;
    if (r >= total) return;

    const float* src;
    float* dst;
    if (r < B)            { src = anchor + (size_t)r * BD;         dst = g_an + (size_t)r * BD; }
    else if (r < 2 * B)   { src = pos    + (size_t)(r - B) * BD;   dst = g_cn + (size_t)(r - B) * BD; }
    else                  { src = neg    + (size_t)(r - 2*B) * BD; dst = g_cn + (size_t)(r - B) * BD; }

    float x[BD];
    #pragma unroll
    for (int k = 0; k < BD; ++k) x[k] = __ldg(src + k);

    float acc0[4] = {0.f, 0.f, 0.f, 0.f};
    float acc1[4] = {0.f, 0.f, 0.f, 0.f};
    #pragma unroll
    for (int i = 0; i < 8; ++i) {
        #pragma unroll
        for (int l = 0; l < 4; ++l)
            acc0[l] = __fadd_rn(acc0[l], __fmul_rn(x[8*i + l],     x[8*i + l]));     // UNFUSED
        #pragma unroll
        for (int l = 0; l < 4; ++l)
            acc1[l] = __fadd_rn(acc1[l], __fmul_rn(x[8*i + 4 + l], x[8*i + 4 + l])); // UNFUSED
    }
    float t0 = __fadd_rn(acc0[0], acc1[0]);
    float t1 = __fadd_rn(acc0[1], acc1[1]);
    float t2 = __fadd_rn(acc0[2], acc1[2]);
    float t3 = __fadd_rn(acc0[3], acc1[3]);
    float s  = __fadd_rn(__fadd_rn(t0, t1), __fadd_rn(t2, t3));   // faddp ladder

    float den = fmaxf(__fsqrt_rn(s), 1e-8f);
    float rcp = __fdiv_rn(1.0f, den);
    #pragma unroll
    for (int k = 0; k < BD; ++k)
        dst[k] = __fmul_rn(x[k], rcp);
}

// ---------------- 2) diagonal (EXACT GEMM chain -> bit-identical) -----------
__global__ void diag_kernel(int B) {
    int r = blockIdx.x * blockDim.x + threadIdx.x;
    if (r >= B) return;
    const float* a = g_an + (size_t)r * BD;
    const float* c = g_cn + (size_t)r * BD;
    float s = 0.f;
    #pragma unroll
    for (int k = 0; k < BD; ++k)
        s = __fmaf_rn(a[k], c[k], s);          // k-ascending fused == GEMM chain
    g_diag[r] = s;
}

// ---------------- 3) GEMM (bit-exact chain FROZEN) + tilemax epilogue -------
__global__ __launch_bounds__(256, 2) void gemm_kernel(int M) {
    extern __shared__ float sm[];
    float* As = sm;                 // [64][TS]
    float* Bs = sm + 64 * TS;       // [64][TS]

    int t = threadIdx.x;            // 256 threads
    int rowBase = blockIdx.y * 128;
    int colBase = blockIdx.x * 128;

    {
        const float4* A4 = reinterpret_cast<const float4*>(g_an + (size_t)rowBase * BD);
        const float4* B4 = reinterpret_cast<const float4*>(g_cn + (size_t)colBase * BD);
        #pragma unroll
        for (int it = 0; it < 8; ++it) {
            int lin = it * 256 + t;
            int r   = lin >> 4;
            int kq  = lin & 15;
            float4 va = A4[r * 16 + kq];
            float4 vb = B4[r * 16 + kq];
            int k = kq * 4;
            As[(k+0)*TS + r] = va.x; As[(k+1)*TS + r] = va.y;
            As[(k+2)*TS + r] = va.z; As[(k+3)*TS + r] = va.w;
            Bs[(k+0)*TS + r] = vb.x; Bs[(k+1)*TS + r] = vb.y;
            Bs[(k+2)*TS + r] = vb.z; Bs[(k+3)*TS + r] = vb.w;
        }
    }
    __syncthreads();

    int tx = t & 15, ty = t >> 4;
    int r0 = ty * 8, c0 = tx * 8;

    float acc[8][8];
    #pragma unroll
    for (int i = 0; i < 8; ++i)
        #pragma unroll
        for (int j = 0; j < 8; ++j)
            acc[i][j] = 0.f;

    #pragma unroll 4
    for (int k = 0; k < 64; ++k) {
        float4 a0 = *reinterpret_cast<const float4*>(&As[k*TS + r0]);
        float4 a1 = *reinterpret_cast<const float4*>(&As[k*TS + r0 + 4]);
        float4 b0 = *reinterpret_cast<const float4*>(&Bs[k*TS + c0]);
        float4 b1 = *reinterpret_cast<const float4*>(&Bs[k*TS + c0 + 4]);

        #define ROW_FMA(i, av)                                   \
            acc[i][0] = __fmaf_rn(av, b0.x, acc[i][0]);          \
            acc[i][1] = __fmaf_rn(av, b0.y, acc[i][1]);          \
            acc[i][2] = __fmaf_rn(av, b0.z, acc[i][2]);          \
            acc[i][3] = __fmaf_rn(av, b0.w, acc[i][3]);          \
            acc[i][4] = __fmaf_rn(av, b1.x, acc[i][4]);          \
            acc[i][5] = __fmaf_rn(av, b1.y, acc[i][5]);          \
            acc[i][6] = __fmaf_rn(av, b1.z, acc[i][6]);          \
            acc[i][7] = __fmaf_rn(av, b1.w, acc[i][7]);
        ROW_FMA(0, a0.x) ROW_FMA(1, a0.y) ROW_FMA(2, a0.z) ROW_FMA(3, a0.w)
        ROW_FMA(4, a1.x) ROW_FMA(5, a1.y) ROW_FMA(6, a1.z) ROW_FMA(7, a1.w)
        #undef ROW_FMA
    }

    #pragma unroll
    for (int i = 0; i < 8; ++i) {
        int row = rowBase + r0 + i;
        float* Cp = g_logits + (size_t)row * M + colBase + c0;
        reinterpret_cast<float4*>(Cp)[0] = make_float4(acc[i][0], acc[i][1], acc[i][2], acc[i][3]);
        reinterpret_cast<float4*>(Cp)[1] = make_float4(acc[i][4], acc[i][5], acc[i][6], acc[i][7]);

        // per-row masked max over this 128-col tile
        float d = g_diag[row];
        float m = -CUDART_INF_F;
        #pragma unroll
        for (int j = 0; j < 8; ++j)
            if (acc[i][j] < d) m = fmaxf(m, acc[i][j]);
        #pragma unroll
        for (int off = 8; off; off >>= 1)
            m = fmaxf(m, __shfl_xor_sync(0xffffffffu, m, off));   // reduce 16 tx lanes
        if (tx == 0)
            g_tilemax[(size_t)row * 128 + blockIdx.x] = m;        // -inf if tile empty
    }
}

// ---------------- 4) topk: single pass + fused zero-fill + scatter ----------
// T = 32nd-largest tile-max: >=32 tiles have max >= T, each contributes >=1
// masked value >= T  =>  >=32 survivors  =>  exact top-32. If <32 finite tile
// maxima, T=-inf and all masked survive. Overflow -> exact gmem fallback.
__global__ __launch_bounds__(256, 5) void topk_kernel(float* __restrict__ out, int B, int M) {
    extern __shared__ float smem[];
    int wl   = threadIdx.x >> 5;
    int w    = (blockIdx.x * blockDim.x + threadIdx.x) >> 5;
    int lane = threadIdx.x & 31;
    if (w >= B) return;

    float* sv = smem + (size_t)wl * TKC;                      // values
    int*   si = (int*)(smem + 8 * TKC) + (size_t)wl * TKC;    // indices

    const float* __restrict__ Lrow = g_logits + (size_t)w * M;
    const float4* __restrict__ L4  = reinterpret_cast<const float4*>(Lrow);
    float4* __restrict__ O4 = reinterpret_cast<float4*>(out + (size_t)w * M);
    float d = __ldg(&g_diag[w]);
    int q4 = M >> 2;                              // 4096 float4s

    // ---- T = 32nd-largest of the 128 tile maxima ----
    float4 tv = reinterpret_cast<const float4*>(g_tilemax + (size_t)w * 128)[lane];
    float a0 = tv.x, a1 = tv.y, a2 = tv.z, a3 = tv.w;
    float T = -CUDART_INF_F;
    #pragma unroll 1
    for (int rnd = 0; rnd < 32; ++rnd) {
        float m = fmaxf(fmaxf(a0, a1), fmaxf(a2, a3));
        float wm = m;
        #pragma unroll
        for (int off = 16; off; off >>= 1)
            wm = fmaxf(wm, __shfl_xor_sync(0xffffffffu, wm, off));
        unsigned msk = __ballot_sync(0xffffffffu, m == wm);
        int leader = __ffs(msk) - 1;
        if (lane == leader) {                     // remove ONE instance
            if      (a0 == wm) a0 = -CUDART_INF_F;
            else if (a1 == wm) a1 = -CUDART_INF_F;
            else if (a2 == wm) a2 = -CUDART_INF_F;
            else               a3 = -CUDART_INF_F;
        }
        T = wm;                                   // after loop: 32nd largest
    }

    // ---- single pass: compact survivors + zero-fill out ----
    const float4 zero4 = make_float4(0.f, 0.f, 0.f, 0.f);
    int cnt = 0;
    #pragma unroll 4
    for (int i = lane; i < q4; i += 32) {
        float4 v = L4[i];
        O4[i] = zero4;
        int jb = i << 2;
        #define COMPACT(val, joff) {                                          \
            bool keep = ((val) < d) && ((val) >= T);                          \
            unsigned mask = __ballot_sync(0xffffffffu, keep);                 \
            if (keep) {                                                       \
                int pos = cnt + __popc(mask & ((1u << lane) - 1u));           \
                if (pos < TKC) { sv[pos] = (val); si[pos] = jb + (joff); }    \
            }                                                                 \
            cnt += __popc(mask);                                              \
        }
        COMPACT(v.x, 0) COMPACT(v.y, 1) COMPACT(v.z, 2) COMPACT(v.w, 3)
        #undef COMPACT
    }
    __syncwarp();

    if (cnt <= TKC) {
        // ---- selection: 32 exact argmax rounds over survivors ----
        for (int it = 0; it < 32; ++it) {
            float bv = -CUDART_INF_F; int bidx = 0x7FFFFFFF; int bslot = -1;
            for (int s = lane; s < cnt; s += 32) {
                float v = sv[s]; int ix = si[s];
                if (v > bv || (v == bv && ix < bidx)) { bv = v; bidx = ix; bslot = s; }
            }
            #pragma unroll
            for (int off = 16; off; off >>= 1) {
                float ov = __shfl_xor_sync(0xffffffffu, bv,    off);
                int   oi = __shfl_xor_sync(0xffffffffu, bidx,  off);
                int   os = __shfl_xor_sync(0xffffffffu, bslot, off);
                if (ov > bv || (ov == bv && oi < bidx)) { bv = ov; bidx = oi; bslot = os; }
            }
            if (bidx == 0x7FFFFFFF) break;
            if (lane == 0) {
                out[(size_t)w * M + bidx] = bv;
                sv[bslot] = -CUDART_INF_F;
                si[bslot] = 0x7FFFFFFF;
            }
            __syncwarp();
        }
    } else {
        // ---- ultra-rare exact fallback: lexicographic descent from gmem ----
        float pv = CUDART_INF_F; int pi = -1;
        for (int it = 0; it < 32; ++it) {
            float bv = -CUDART_INF_F; int bidx = 0x7FFFFFFF;
            for (int i = lane; i < M; i += 32) {
                float v = Lrow[i];
                if (v >= d) continue;
                bool after = (v < pv) || (v == pv && i > pi);
                if (!after) continue;
                if (v > bv || (v == bv && i < bidx)) { bv = v; bidx = i; }
            }
            #pragma unroll
            for (int off = 16; off; off >>= 1) {
                float ov = __shfl_xor_sync(0xffffffffu, bv,   off);
                int   oi = __shfl_xor_sync(0xffffffffu, bidx, off);
                if (ov > bv || (ov == bv && oi < bidx)) { bv = ov; bidx = oi; }
            }
            if (bidx == 0x7FFFFFFF) break;
            if (lane == 0) out[(size_t)w * M + bidx] = bv;
            pv = bv; pi = bidx;
        }
    }
}

// ---------------- launcher ---------------------------------------------------
extern "C" void kernel_launch(void* const* d_in, const int* in_sizes, int n_in,
                              void* d_out, int out_size) {
    const float* anchor = (const float*)d_in[0];
    const float* pos    = (const float*)d_in[1];
    const float* neg    = (const float*)d_in[2];
    float* out = (float*)d_out;

    int B  = in_sizes[0] / BD;   // 8192
    int Nn = in_sizes[2] / BD;   // 8192
    int M  = B + Nn;             // 16384

    // #1 normalize (numerics frozen)
    int totalRows = 2 * B + Nn;
    normalize_kernel<<<(totalRows + 127) / 128, 128>>>(anchor, pos, neg, B, Nn);

    // #2 diagonal (bit-identical chain)
    diag_kernel<<<(B + 127) / 128, 128>>>(B);

    // #3 GEMM + tilemax epilogue
    int smemBytes = 2 * 64 * TS * (int)sizeof(float);   // 67584
    cudaFuncSetAttribute(gemm_kernel, cudaFuncAttributeMaxDynamicSharedMemorySize, smemBytes);
    dim3 ggrid(M / 128, B / 128);
    gemm_kernel<<<ggrid, 256, smemBytes>>>(M);

    // #4 topk: single pass + fused zero-fill + scatter   <-- ncu target
    int tkSmem = 8 * TKC * 2 * (int)sizeof(float);      // 32 KB
    cudaFuncSetAttribute(topk_kernel, cudaFuncAttributeMaxDynamicSharedMemorySize, tkSmem);
    topk_kernel<<<(B * 32 + 255) / 256, 256, tkSmem>>>(out, B, M);
}